// round 6
// baseline (speedup 1.0000x reference)
#include <cuda_runtime.h>

#define BB   32
#define C1   64
#define GG   256
#define HW   122
#define W0IN 128
#define CLU  4      // width slices (CTAs) per batch
#define WSL  31     // nominal slice width (last slice = 29)
#define HSTR 36     // hbuf row stride (floats), needs >= Ws+2

typedef unsigned long long u64;

// ---------------- scratch (static __device__: allocation-free) ----------------
__device__ float g_feat[BB * C1 * HW * HW];        // ~122 MB
__device__ float g_i2s[BB * GG * HW * HW];         // ~488 MB (gates incl. both biases)
__device__ float g_halo[BB][2][CLU][C1];           // per-row boundary columns

// ---------------- math helpers ----------------
__device__ __forceinline__ float tanha(float x) {
    float y;
    asm("tanh.approx.f32 %0, %1;" : "=f"(y) : "f"(x));
    return y;
}
__device__ __forceinline__ float sigmf(float x) {
    return 0.5f * tanha(0.5f * x) + 0.5f;
}
__device__ __forceinline__ u64 pk2(float lo, float hi) {
    u64 r;
    asm("mov.b64 %0, {%1, %2};" : "=l"(r) : "f"(lo), "f"(hi));
    return r;
}
__device__ __forceinline__ void fma2(u64& d, u64 a, u64 b) {
    asm("fma.rn.f32x2 %0, %1, %2, %0;" : "+l"(d) : "l"(a), "l"(b));
}
__device__ __forceinline__ void unpk2(u64 v, float& lo, float& hi) {
    asm("mov.b64 {%0, %1}, %2;" : "=f"(lo), "=f"(hi) : "l"(v));
}

// ---------------- conv1: 7x7 valid, [B,1,128,128] -> [B,64,122,122] ----------------
__global__ __launch_bounds__(256) void conv1_kernel(
    const float* __restrict__ x, const float* __restrict__ w1, const float* __restrict__ b1)
{
    __shared__ float xs[7][136];
    __shared__ float ws[C1 * 49];
    __shared__ float bs[C1];

    int bh = blockIdx.x;
    int b = bh / HW, h = bh % HW;
    int t = threadIdx.x;

    for (int i = t; i < C1 * 49; i += 256) ws[i] = w1[i];
    if (t < C1) bs[t] = b1[t];
    for (int i = t; i < 7 * 136; i += 256) {
        int r = i / 136, cw = i % 136;
        xs[r][cw] = (cw < W0IN) ? x[(b * W0IN + (h + r)) * W0IN + cw] : 0.f;
    }
    __syncthreads();

    for (int task = t; task < C1 * 32; task += 256) {
        int c = task >> 5;
        int wt = task & 31;
        int w0 = wt * 4;
        float a0 = 0.f, a1 = 0.f, a2 = 0.f, a3 = 0.f;
#pragma unroll
        for (int kh = 0; kh < 7; kh++) {
            float4 va = *(const float4*)&xs[kh][w0];
            float4 vb = *(const float4*)&xs[kh][w0 + 4];
            float2 vc = *(const float2*)&xs[kh][w0 + 8];
            float f[10] = {va.x, va.y, va.z, va.w, vb.x, vb.y, vb.z, vb.w, vc.x, vc.y};
            const float* wr = &ws[c * 49 + kh * 7];
#pragma unroll
            for (int kw = 0; kw < 7; kw++) {
                float wv = wr[kw];
                a0 += wv * f[kw];
                a1 += wv * f[kw + 1];
                a2 += wv * f[kw + 2];
                a3 += wv * f[kw + 3];
            }
        }
        float bb = bs[c];
        int base = ((b * C1 + c) * HW + h) * HW + w0;
        if (w0 + 0 < HW) g_feat[base + 0] = a0 + bb;
        if (w0 + 1 < HW) g_feat[base + 1] = a1 + bb;
        if (w0 + 2 < HW) g_feat[base + 2] = a2 + bb;
        if (w0 + 3 < HW) g_feat[base + 3] = a3 + bb;
    }
}

// ---------------- i2s: (1,3) conv SAME-width (R2 version, measured-good) ----------------
__global__ __launch_bounds__(256) void i2s_kernel(
    const float* __restrict__ w, const float* __restrict__ bi, const float* __restrict__ bs2)
{
    extern __shared__ float sm[];
    float* fp = sm;                        // [64][124] padded feat row
    float* ws = sm + C1 * 124 + 8;         // [128][192]
    float* bc = ws + 128 * 192;            // [128]

    int bx = blockIdx.x;
    int half = bx & 1;
    int bh = bx >> 1;
    int b = bh / HW, h = bh % HW;
    int t = threadIdx.x;

    for (int i = t; i < C1 * 124; i += 256) {
        int c = i / 124, cw = i % 124;
        fp[i] = (cw >= 1 && cw <= HW) ? g_feat[((b * C1 + c) * HW + h) * HW + (cw - 1)] : 0.f;
    }
    if (t < 8) fp[C1 * 124 + t] = 0.f;
    for (int i = t; i < 128 * 192; i += 256) ws[i] = w[(half * 128) * 192 + i];
    if (t < 128) {
        int og = half * 128 + t;
        bc[t] = bi[og] + bs2[og];
    }
    __syncthreads();

    int wt = t & 31;
    int rt0 = t >> 5;
    int w0 = wt * 4;
    bool active = (w0 < HW);

    for (int pass = 0; pass < 2; pass++) {
        int oc0 = (rt0 + 8 * pass) * 8;
        if (active) {
            u64 aA[8], aB[8];
#pragma unroll
            for (int i = 0; i < 8; i++) { aA[i] = 0ull; aB[i] = 0ull; }
#pragma unroll 2
            for (int c = 0; c < C1; c++) {
                const float* fr = &fp[c * 124 + w0];
                float4 va = *(const float4*)fr;
                float2 vb = *(const float2*)(fr + 4);
                u64 P0 = pk2(va.x, va.y), P1 = pk2(va.y, va.z), P2 = pk2(va.z, va.w);
                u64 P3 = pk2(va.w, vb.x), P4 = pk2(vb.x, vb.y);
                const float* wr = &ws[oc0 * 192 + c * 3];
#pragma unroll
                for (int i = 0; i < 8; i++) {
                    float wv0 = wr[i * 192 + 0];
                    float wv1 = wr[i * 192 + 1];
                    float wv2 = wr[i * 192 + 2];
                    u64 s0 = pk2(wv0, wv0), s1 = pk2(wv1, wv1), s2 = pk2(wv2, wv2);
                    fma2(aA[i], s0, P0);  fma2(aB[i], s0, P2);
                    fma2(aA[i], s1, P1);  fma2(aB[i], s1, P3);
                    fma2(aA[i], s2, P2);  fma2(aB[i], s2, P4);
                }
            }
#pragma unroll
            for (int i = 0; i < 8; i++) {
                int ocl = oc0 + i;
                int og = half * 128 + ocl;
                float bb = bc[ocl];
                float r0, r1, r2, r3;
                unpk2(aA[i], r0, r1);
                unpk2(aB[i], r2, r3);
                int base = ((b * GG + og) * HW + h) * HW + w0;
                if (w0 + 0 < HW) g_i2s[base + 0] = r0 + bb;
                if (w0 + 1 < HW) g_i2s[base + 1] = r1 + bb;
                if (w0 + 2 < HW) g_i2s[base + 2] = r2 + bb;
                if (w0 + 3 < HW) g_i2s[base + 3] = r3 + bb;
            }
        }
    }
}

// ---------------- persistent scan v3: 1024 threads, 32 warps/SM ----------------
// Cluster = batch (4 CTAs, width slices 31/31/31/29). h stays in smem; halo
// columns via L2 + cluster barrier. Thread = (2 channels, 4 gate types, 1 w):
// warp = channel-pair, lane = w. Weight pairs load directly as LDS.64 from
// transposed wT (broadcast); only h needs splat MOVs. 8 warps/SMSP for latency.
__global__ __launch_bounds__(1024, 1) __cluster_dims__(CLU, 1, 1)
void scan_kernel(const float* __restrict__ ws2, float* __restrict__ out)
{
    extern __shared__ float sm[];
    float* wT   = sm;                         // [192][256]  wT[k][g] = ws2[g][k]
    float* hbuf = sm + 192 * GG;              // [2][64][HSTR]

    int t  = threadIdx.x;
    int bx = blockIdx.x;
    int b  = bx / CLU;
    int jr = bx % CLU;
    int ws_off = jr * WSL;                    // slice start (global w)
    int Ws = (jr == CLU - 1) ? (HW - (CLU - 1) * WSL) : WSL;   // 31/31/31/29

    // transposed weights (one-time)
    for (int i = t; i < 192 * GG; i += 1024) {
        int k = i >> 8, g = i & 255;
        wT[i] = ws2[g * 192 + k];
    }
    // zero h buffers
    for (int i = t; i < 2 * C1 * HSTR; i += 1024) hbuf[i] = 0.f;
    __syncthreads();

    int wid  = t >> 5;            // warp -> channel pair (0..31)
    int lane = t & 31;            // lane -> local w
    int ch0  = wid * 2;
    int wg   = ws_off + lane;     // global w
    bool active = (lane < Ws);

    float cst[2] = {0.f, 0.f};
    const int HW2 = HW * HW;

    for (int r = 0; r < HW; r++) {
        int pb = r & 1;           // read buffer (h of row r-1)
        int cb = pb ^ 1;          // write buffer (h of row r)
        const float* hp = hbuf + pb * C1 * HSTR;
        float*       hn = hbuf + cb * C1 * HSTR;

        // ---- prefetch i2s gates for this row (hides DRAM under the GEMM)
        float pre[4][2];
        if (active) {
            int gb = (b * GG) * HW2 + r * HW + wg;
#pragma unroll
            for (int ty = 0; ty < 4; ty++)
#pragma unroll
                for (int cc = 0; cc < 2; cc++)
                    pre[ty][cc] = __ldcg(&g_i2s[gb + (ty * 64 + ch0 + cc) * HW2]);
        }

        // ---- GEMM: gates[ty][ch0,ch0+1] at w = wg
        u64 acc[4];
#pragma unroll
        for (int ty = 0; ty < 4; ty++) acc[ty] = 0ull;

#pragma unroll 4
        for (int c = 0; c < C1; c++) {
            const float* hr = &hp[c * HSTR + lane];   // h(wg-1), h(wg), h(wg+1)
            float h0 = hr[0], h1 = hr[1], h2 = hr[2];
            u64 s0 = pk2(h0, h0), s1 = pk2(h1, h1), s2 = pk2(h2, h2);
            const float* wk = &wT[(c * 3) * GG + ch0];
#pragma unroll
            for (int ty = 0; ty < 4; ty++) {
                float2 q0 = *(const float2*)(wk + ty * 64);
                float2 q1 = *(const float2*)(wk + ty * 64 + GG);
                float2 q2 = *(const float2*)(wk + ty * 64 + 2 * GG);
                fma2(acc[ty], pk2(q0.x, q0.y), s0);
                fma2(acc[ty], pk2(q1.x, q1.y), s1);
                fma2(acc[ty], pk2(q2.x, q2.y), s2);
            }
        }

        // ---- LSTM epilogue (all 4 types local to this thread)
        if (active) {
            float gate[4][2];
#pragma unroll
            for (int ty = 0; ty < 4; ty++)
                unpk2(acc[ty], gate[ty][0], gate[ty][1]);
#pragma unroll
            for (int cc = 0; cc < 2; cc++) {
                float go = gate[0][cc] + pre[0][cc];
                float gf = gate[1][cc] + pre[1][cc];
                float gi = gate[2][cc] + pre[2][cc];
                float gg = gate[3][cc] + pre[3][cc];
                float cn = sigmf(gf) * cst[cc] + sigmf(gi) * tanha(gg);
                float hv = sigmf(go) * tanha(cn);
                cst[cc] = cn;
                int ch = ch0 + cc;
                hn[ch * HSTR + lane + 1] = hv;                       // local h
                out[((b * C1 + ch) * HW + r) * HW + wg] = hv;
                if (lane == 0)      __stcg(&g_halo[b][0][jr][ch], hv);   // left edge
                if (lane == Ws - 1) __stcg(&g_halo[b][1][jr][ch], hv);   // right edge
            }
        }

        // ---- release local h + edges; acquire peers' edges
        asm volatile("barrier.cluster.arrive.aligned;" ::: "memory");
        asm volatile("barrier.cluster.wait.aligned;"   ::: "memory");

        // ---- halo fetch into hn cols 0 and Ws+1
        if (t < C1) {
            float v = (jr > 0) ? __ldcg(&g_halo[b][1][jr - 1][t]) : 0.f;
            hn[t * HSTR + 0] = v;
        } else if (t < 2 * C1) {
            int c = t - C1;
            float v = (jr < CLU - 1) ? __ldcg(&g_halo[b][0][jr + 1][c]) : 0.f;
            hn[c * HSTR + Ws + 1] = v;
        }
        __syncthreads();
    }
}

// ---------------- launch ----------------
extern "C" void kernel_launch(void* const* d_in, const int* in_sizes, int n_in,
                              void* d_out, int out_size)
{
    const float* x   = (const float*)d_in[0];
    const float* c1w = (const float*)d_in[1];
    const float* c1b = (const float*)d_in[2];
    const float* i2w = (const float*)d_in[3];
    const float* i2b = (const float*)d_in[4];
    const float* s2w = (const float*)d_in[5];
    const float* s2b = (const float*)d_in[6];
    float* out = (float*)d_out;

    const int i2s_smem  = (C1 * 124 + 8 + 128 * 192 + 128) * sizeof(float);     // ~130.6 KB
    const int scan_smem = (192 * GG + 2 * C1 * HSTR) * sizeof(float);           // ~210 KB
    cudaFuncSetAttribute(i2s_kernel,  cudaFuncAttributeMaxDynamicSharedMemorySize, i2s_smem);
    cudaFuncSetAttribute(scan_kernel, cudaFuncAttributeMaxDynamicSharedMemorySize, scan_smem);

    conv1_kernel<<<BB * HW, 256>>>(x, c1w, c1b);
    i2s_kernel<<<BB * HW * 2, 256, i2s_smem>>>(i2w, i2b, s2b);
    scan_kernel<<<BB * CLU, 1024, scan_smem>>>(s2w, out);
}

// round 7
// speedup vs baseline: 1.0531x; 1.0531x over previous
#include <cuda_runtime.h>
#include <cstdint>

#define BB   32
#define C1   64
#define GG   256
#define HW   122
#define W0IN 128
#define CLU  4      // width slices (CTAs) per batch
#define WSL  31     // nominal slice width (last slice = 29)
#define HSTR 36     // hbuf row stride (floats), >= 34

typedef unsigned long long u64;

// ---------------- scratch (static __device__: allocation-free) ----------------
__device__ float g_feat[BB * C1 * HW * HW];        // ~122 MB
__device__ float g_i2s[BB * GG * HW * HW];         // ~488 MB (gates incl. both biases)

// ---------------- math helpers ----------------
__device__ __forceinline__ float tanha(float x) {
    float y;
    asm("tanh.approx.f32 %0, %1;" : "=f"(y) : "f"(x));
    return y;
}
__device__ __forceinline__ float sigmf(float x) {
    return 0.5f * tanha(0.5f * x) + 0.5f;
}
__device__ __forceinline__ u64 pk2(float lo, float hi) {
    u64 r;
    asm("mov.b64 %0, {%1, %2};" : "=l"(r) : "f"(lo), "f"(hi));
    return r;
}
__device__ __forceinline__ void fma2(u64& d, u64 a, u64 b) {
    asm("fma.rn.f32x2 %0, %1, %2, %0;" : "+l"(d) : "l"(a), "l"(b));
}
__device__ __forceinline__ void unpk2(u64 v, float& lo, float& hi) {
    asm("mov.b64 {%0, %1}, %2;" : "=f"(lo), "=f"(hi) : "l"(v));
}
__device__ __forceinline__ uint32_t smem_u32(const void* p) {
    uint32_t a;
    asm("{ .reg .u64 tt; cvta.to.shared.u64 tt, %1; cvt.u32.u64 %0, tt; }"
        : "=r"(a) : "l"(p));
    return a;
}
// store a float into peer CTA's smem (same offset), ordered by the cluster barrier
__device__ __forceinline__ void st_dsmem(uint32_t laddr, uint32_t rank, float v) {
    asm volatile(
        "{ .reg .b32 ra; mapa.shared::cluster.u32 ra, %0, %1; "
        "st.shared::cluster.f32 [ra], %2; }"
        :: "r"(laddr), "r"(rank), "f"(v) : "memory");
}

// ---------------- conv1: 7x7 valid, [B,1,128,128] -> [B,64,122,122] ----------------
__global__ __launch_bounds__(256) void conv1_kernel(
    const float* __restrict__ x, const float* __restrict__ w1, const float* __restrict__ b1)
{
    __shared__ float xs[7][136];
    __shared__ float ws[C1 * 49];
    __shared__ float bs[C1];

    int bh = blockIdx.x;
    int b = bh / HW, h = bh % HW;
    int t = threadIdx.x;

    for (int i = t; i < C1 * 49; i += 256) ws[i] = w1[i];
    if (t < C1) bs[t] = b1[t];
    for (int i = t; i < 7 * 136; i += 256) {
        int r = i / 136, cw = i % 136;
        xs[r][cw] = (cw < W0IN) ? x[(b * W0IN + (h + r)) * W0IN + cw] : 0.f;
    }
    __syncthreads();

    for (int task = t; task < C1 * 32; task += 256) {
        int c = task >> 5;
        int wt = task & 31;
        int w0 = wt * 4;
        float a0 = 0.f, a1 = 0.f, a2 = 0.f, a3 = 0.f;
#pragma unroll
        for (int kh = 0; kh < 7; kh++) {
            float4 va = *(const float4*)&xs[kh][w0];
            float4 vb = *(const float4*)&xs[kh][w0 + 4];
            float2 vc = *(const float2*)&xs[kh][w0 + 8];
            float f[10] = {va.x, va.y, va.z, va.w, vb.x, vb.y, vb.z, vb.w, vc.x, vc.y};
            const float* wr = &ws[c * 49 + kh * 7];
#pragma unroll
            for (int kw = 0; kw < 7; kw++) {
                float wv = wr[kw];
                a0 += wv * f[kw];
                a1 += wv * f[kw + 1];
                a2 += wv * f[kw + 2];
                a3 += wv * f[kw + 3];
            }
        }
        float bb = bs[c];
        int base = ((b * C1 + c) * HW + h) * HW + w0;
        if (w0 + 0 < HW) g_feat[base + 0] = a0 + bb;
        if (w0 + 1 < HW) g_feat[base + 1] = a1 + bb;
        if (w0 + 2 < HW) g_feat[base + 2] = a2 + bb;
        if (w0 + 3 < HW) g_feat[base + 3] = a3 + bb;
    }
}

// ---------------- i2s: (1,3) conv SAME-width (measured at FFMA2 floor; unchanged) ----
__global__ __launch_bounds__(256) void i2s_kernel(
    const float* __restrict__ w, const float* __restrict__ bi, const float* __restrict__ bs2)
{
    extern __shared__ float sm[];
    float* fp = sm;                        // [64][124] padded feat row
    float* ws = sm + C1 * 124 + 8;         // [128][192]
    float* bc = ws + 128 * 192;            // [128]

    int bx = blockIdx.x;
    int half = bx & 1;
    int bh = bx >> 1;
    int b = bh / HW, h = bh % HW;
    int t = threadIdx.x;

    for (int i = t; i < C1 * 124; i += 256) {
        int c = i / 124, cw = i % 124;
        fp[i] = (cw >= 1 && cw <= HW) ? g_feat[((b * C1 + c) * HW + h) * HW + (cw - 1)] : 0.f;
    }
    if (t < 8) fp[C1 * 124 + t] = 0.f;
    for (int i = t; i < 128 * 192; i += 256) ws[i] = w[(half * 128) * 192 + i];
    if (t < 128) {
        int og = half * 128 + t;
        bc[t] = bi[og] + bs2[og];
    }
    __syncthreads();

    int wt = t & 31;
    int rt0 = t >> 5;
    int w0 = wt * 4;
    bool active = (w0 < HW);

    for (int pass = 0; pass < 2; pass++) {
        int oc0 = (rt0 + 8 * pass) * 8;
        if (active) {
            u64 aA[8], aB[8];
#pragma unroll
            for (int i = 0; i < 8; i++) { aA[i] = 0ull; aB[i] = 0ull; }
#pragma unroll 2
            for (int c = 0; c < C1; c++) {
                const float* fr = &fp[c * 124 + w0];
                float4 va = *(const float4*)fr;
                float2 vb = *(const float2*)(fr + 4);
                u64 P0 = pk2(va.x, va.y), P1 = pk2(va.y, va.z), P2 = pk2(va.z, va.w);
                u64 P3 = pk2(va.w, vb.x), P4 = pk2(vb.x, vb.y);
                const float* wr = &ws[oc0 * 192 + c * 3];
#pragma unroll
                for (int i = 0; i < 8; i++) {
                    float wv0 = wr[i * 192 + 0];
                    float wv1 = wr[i * 192 + 1];
                    float wv2 = wr[i * 192 + 2];
                    u64 s0 = pk2(wv0, wv0), s1 = pk2(wv1, wv1), s2 = pk2(wv2, wv2);
                    fma2(aA[i], s0, P0);  fma2(aB[i], s0, P2);
                    fma2(aA[i], s1, P1);  fma2(aB[i], s1, P3);
                    fma2(aA[i], s2, P2);  fma2(aB[i], s2, P4);
                }
            }
#pragma unroll
            for (int i = 0; i < 8; i++) {
                int ocl = oc0 + i;
                int og = half * 128 + ocl;
                float bb = bc[ocl];
                float r0, r1, r2, r3;
                unpk2(aA[i], r0, r1);
                unpk2(aB[i], r2, r3);
                int base = ((b * GG + og) * HW + h) * HW + w0;
                if (w0 + 0 < HW) g_i2s[base + 0] = r0 + bb;
                if (w0 + 1 < HW) g_i2s[base + 1] = r1 + bb;
                if (w0 + 2 < HW) g_i2s[base + 2] = r2 + bb;
                if (w0 + 3 < HW) g_i2s[base + 3] = r3 + bb;
            }
        }
    }
}

// ---------------- persistent scan v4: pre-paired weights + DSMEM halo ----------------
// Cluster = batch (4 CTAs, slices 31/31/31/29). 512 threads, 1 CTA/SM.
// Weights stored in smem as u64 pairs over adjacent gates -> zero pack ALU for
// weights; per-(thread,c): 24 fma2 + 12 LDS.128 + 3 pk2(h). Halo columns are
// pushed straight into the neighbor CTA's smem h-buffer (mapa + st.shared::cluster),
// ordered by the per-row cluster barrier -> nothing on the post-barrier path.
__global__ __launch_bounds__(512, 1) __cluster_dims__(CLU, 1, 1)
void scan_kernel(const float* __restrict__ ws2, float* __restrict__ out)
{
    extern __shared__ float sm[];
    u64*   wP   = (u64*)sm;                   // [192][128] paired weights (196.6 KB)
    float* hbuf = sm + 192 * GG;              // [2][64][HSTR]

    int t  = threadIdx.x;
    int bx = blockIdx.x;
    int b  = bx / CLU;
    int jr = bx % CLU;
    int ws_off = jr * WSL;
    int Ws = (jr == CLU - 1) ? (HW - (CLU - 1) * WSL) : WSL;   // 31/31/31/29

    // paired weights: wP[k][p] = (ws2[2p][k], ws2[2p+1][k]),  g = ty*64+ch
    for (int i = t; i < 192 * 128; i += 512) {
        int k = i >> 7, p = i & 127;
        wP[i] = pk2(ws2[(2 * p) * 192 + k], ws2[(2 * p + 1) * 192 + k]);
    }
    // zero both h buffers (halo cols of boundary CTAs stay zero forever)
    for (int i = t; i < 2 * C1 * HSTR; i += 512) hbuf[i] = 0.f;
    __syncthreads();

    int wid  = t >> 5;            // warp -> channel group (4 channels)
    int lane = t & 31;            // lane -> local w
    int ch0  = wid * 4;
    int wg   = ws_off + lane;     // global w
    bool active = (lane < Ws);

    uint32_t hbuf_su = smem_u32(hbuf);

    float cst[4] = {0.f, 0.f, 0.f, 0.f};
    const int HW2 = HW * HW;

    for (int r = 0; r < HW; r++) {
        int pb = r & 1;
        int cb = pb ^ 1;
        const float* hp = hbuf + pb * C1 * HSTR;
        float*       hn = hbuf + cb * C1 * HSTR;
        uint32_t hn_su = hbuf_su + (uint32_t)(cb * C1 * HSTR) * 4u;

        // ---- prefetch i2s gates (independent of h; hidden under the GEMM)
        float pre[4][4];
        if (active) {
            int gb = (b * GG) * HW2 + r * HW + wg;
#pragma unroll
            for (int ty = 0; ty < 4; ty++)
#pragma unroll
                for (int cc = 0; cc < 4; cc++)
                    pre[ty][cc] = __ldcg(&g_i2s[gb + (ty * 64 + ch0 + cc) * HW2]);
        }

        // ---- GEMM: gates[ty][ch0..ch0+3] at w = wg
        u64 aA[4], aB[4];
#pragma unroll
        for (int ty = 0; ty < 4; ty++) { aA[ty] = 0ull; aB[ty] = 0ull; }

#pragma unroll 4
        for (int c = 0; c < C1; c++) {
            const float* hr = &hp[c * HSTR + lane];   // h(wg-1), h(wg), h(wg+1)
            float h0 = hr[0], h1 = hr[1], h2 = hr[2];
            u64 s0 = pk2(h0, h0), s1 = pk2(h1, h1), s2 = pk2(h2, h2);
            const u64* wk = &wP[(c * 3) * 128 + (wid << 1)];
#pragma unroll
            for (int ty = 0; ty < 4; ty++) {
                ulonglong2 u0 = *(const ulonglong2*)(wk + ty * 32);          // k=0 pair(A,B)
                ulonglong2 u1 = *(const ulonglong2*)(wk + ty * 32 + 128);    // k=1
                ulonglong2 u2 = *(const ulonglong2*)(wk + ty * 32 + 256);    // k=2
                fma2(aA[ty], u0.x, s0);  fma2(aB[ty], u0.y, s0);
                fma2(aA[ty], u1.x, s1);  fma2(aB[ty], u1.y, s1);
                fma2(aA[ty], u2.x, s2);  fma2(aB[ty], u2.y, s2);
            }
        }

        // ---- LSTM epilogue
        if (active) {
            float gate[4][4];
#pragma unroll
            for (int ty = 0; ty < 4; ty++) {
                unpk2(aA[ty], gate[ty][0], gate[ty][1]);
                unpk2(aB[ty], gate[ty][2], gate[ty][3]);
            }
#pragma unroll
            for (int cc = 0; cc < 4; cc++) {
                float go = gate[0][cc] + pre[0][cc];
                float gf = gate[1][cc] + pre[1][cc];
                float gi = gate[2][cc] + pre[2][cc];
                float gg = gate[3][cc] + pre[3][cc];
                float cn = sigmf(gf) * cst[cc] + sigmf(gi) * tanha(gg);
                float hv = sigmf(go) * tanha(cn);
                cst[cc] = cn;
                int ch = ch0 + cc;
                hn[ch * HSTR + lane + 1] = hv;                          // local
                out[((b * C1 + ch) * HW + r) * HW + wg] = hv;
                // halo pushes straight into neighbor CTA's smem h-buffer
                if (lane == 0 && jr > 0)                 // -> left peer's col 32 (its Ws+1)
                    st_dsmem(hn_su + (uint32_t)(ch * HSTR + 32) * 4u, jr - 1, hv);
                if (lane == Ws - 1 && jr < CLU - 1)      // -> right peer's col 0
                    st_dsmem(hn_su + (uint32_t)(ch * HSTR + 0) * 4u, jr + 1, hv);
            }
        }

        // one barrier per row: orders local STS + remote DSMEM stores cluster-wide
        asm volatile("barrier.cluster.arrive.aligned;" ::: "memory");
        asm volatile("barrier.cluster.wait.aligned;"   ::: "memory");
    }
}

// ---------------- launch ----------------
extern "C" void kernel_launch(void* const* d_in, const int* in_sizes, int n_in,
                              void* d_out, int out_size)
{
    const float* x   = (const float*)d_in[0];
    const float* c1w = (const float*)d_in[1];
    const float* c1b = (const float*)d_in[2];
    const float* i2w = (const float*)d_in[3];
    const float* i2b = (const float*)d_in[4];
    const float* s2w = (const float*)d_in[5];
    const float* s2b = (const float*)d_in[6];
    float* out = (float*)d_out;

    const int i2s_smem  = (C1 * 124 + 8 + 128 * 192 + 128) * sizeof(float);     // ~130.6 KB
    const int scan_smem = 192 * 128 * 8 + 2 * C1 * HSTR * 4;                    // ~210 KB
    cudaFuncSetAttribute(i2s_kernel,  cudaFuncAttributeMaxDynamicSharedMemorySize, i2s_smem);
    cudaFuncSetAttribute(scan_kernel, cudaFuncAttributeMaxDynamicSharedMemorySize, scan_smem);

    conv1_kernel<<<BB * HW, 256>>>(x, c1w, c1b);
    i2s_kernel<<<BB * HW * 2, 256, i2s_smem>>>(i2w, i2b, s2b);
    scan_kernel<<<BB * CLU, 512, scan_smem>>>(s2w, out);
}